// round 12
// baseline (speedup 1.0000x reference)
#include <cuda_runtime.h>
#include <cuda_bf16.h>

// ----------------------------------------------------------------------------
// QCNN, round 11: conv takes 2 sample-pairs per 512-thread CTA (weight staging
// + launch overhead amortized 2x, same per-warp structure); dense forced to
// 4 CTAs/SM via launch_bounds.
// ----------------------------------------------------------------------------

typedef unsigned long long u64;

__device__ __align__(16) float g_qw1[64];      // [co*4 + ci*2 + k]
__device__ __align__(16) float g_qw2[768];     // [(ci*3+k)*16 + co]
__device__ __align__(16) float g_qw3[2560];    // [(ci*5+k)*32 + co]
__device__ __align__(16) float g_qw4[5120];    // [(ci*5+k)*32 + co]
__device__ __align__(16) float g_qwd[55296];   // [idx=pq*32+co][oc*2+h]  h: +32
__device__ __align__(16) float g_qwo[64];
__device__ float g_scale[6];
__device__ __align__(16) u64   g_P2[16384 * 864];  // [pair][pq*32+co] f32x2

// ---- f32x2 helpers ---------------------------------------------------------
__device__ __forceinline__ u64 ffma2(u64 a, u64 b, u64 c) {
    u64 d;
    asm("fma.rn.f32x2 %0, %1, %2, %3;" : "=l"(d) : "l"(a), "l"(b), "l"(c));
    return d;
}
__device__ __forceinline__ u64 add2(u64 a, u64 b) {
    u64 d;
    asm("add.rn.f32x2 %0, %1, %2;" : "=l"(d) : "l"(a), "l"(b));
    return d;
}
__device__ __forceinline__ u64 pack2(float x, float y) {
    u64 d;
    asm("mov.b64 %0, {%1, %2};" : "=l"(d) : "f"(x), "f"(y));
    return d;
}
__device__ __forceinline__ float2 unpack2(u64 v) {
    float2 f;
    asm("mov.b64 {%0, %1}, %2;" : "=f"(f.x), "=f"(f.y) : "l"(v));
    return f;
}
__device__ __forceinline__ u64 dup2(float w) { return pack2(w, w); }
__device__ __forceinline__ u64 lrelu2(u64 v) {
    float2 f = unpack2(v);
    f.x = f.x > 0.0f ? f.x : 0.1f * f.x;
    f.y = f.y > 0.0f ? f.y : 0.1f * f.y;
    return pack2(f.x, f.y);
}
__device__ __forceinline__ u64 max2(u64 a, u64 b) {
    float2 fa = unpack2(a), fb = unpack2(b);
    return pack2(fmaxf(fa.x, fb.x), fmaxf(fa.y, fb.y));
}
__device__ __forceinline__ ulonglong2 lds2(const u64* p) {
    return *reinterpret_cast<const ulonglong2*>(p);
}

// ---- prep phase A: per-tensor scale (max|w| / 127) -------------------------
__global__ void scale_kernel(const float* __restrict__ w1,
                             const float* __restrict__ w2,
                             const float* __restrict__ w3,
                             const float* __restrict__ w4,
                             const float* __restrict__ wd,
                             const float* __restrict__ wo) {
    __shared__ float red[256];
    int b = blockIdx.x, tid = threadIdx.x;
    const float* src; int n;
    if (b == 0)      { src = w1; n = 64; }
    else if (b == 1) { src = w2; n = 768; }
    else if (b == 2) { src = w3; n = 2560; }
    else if (b == 3) { src = w4; n = 5120; }
    else if (b == 4) { src = wd; n = 55296; }
    else             { src = wo; n = 64; }
    float m = 0.0f;
    for (int i = tid; i < n; i += 256) m = fmaxf(m, fabsf(src[i]));
    red[tid] = m;
    __syncthreads();
    for (int s = 128; s > 0; s >>= 1) {
        if (tid < s) red[tid] = fmaxf(red[tid], red[tid + s]);
        __syncthreads();
    }
    if (tid == 0) g_scale[b] = red[0] / 127.0f;
}

// ---- prep phase B: quantize + permute, fully parallel ----------------------
__global__ void quantize_kernel(const float* __restrict__ w1,
                                const float* __restrict__ w2,
                                const float* __restrict__ w3,
                                const float* __restrict__ w4,
                                const float* __restrict__ wd,
                                const float* __restrict__ wo) {
    int blk = blockIdx.x, tid = threadIdx.x;
    int b, i;
    const float* src; float* dst; int n;
    if (blk < 1)        { b = 0; src = w1; dst = g_qw1; n = 64;    i = blk * 256 + tid; }
    else if (blk < 4)   { b = 1; src = w2; dst = g_qw2; n = 768;   i = (blk - 1) * 256 + tid; }
    else if (blk < 14)  { b = 2; src = w3; dst = g_qw3; n = 2560;  i = (blk - 4) * 256 + tid; }
    else if (blk < 34)  { b = 3; src = w4; dst = g_qw4; n = 5120;  i = (blk - 14) * 256 + tid; }
    else if (blk < 250) { b = 4; src = wd; dst = g_qwd; n = 55296; i = (blk - 34) * 256 + tid; }
    else                { b = 5; src = wo; dst = g_qwo; n = 64;    i = (blk - 250) * 256 + tid; }
    if (i >= n) return;
    float scale = g_scale[b];
    float q = rintf(src[i] / scale);               // round half-even == jnp.round
    q = fminf(fmaxf(q, -127.0f), 127.0f) * scale;
    int di = i;
    if (b == 1) {
        int co = i / 48, r = i - co * 48, ci = r / 3, k = r - ci * 3;
        di = (ci * 3 + k) * 16 + co;
    } else if (b == 2) {
        int co = i / 80, r = i - co * 80, ci = r / 5, k = r - ci * 5;
        di = (ci * 5 + k) * 32 + co;
    } else if (b == 3) {
        int co = i / 160, r = i - co * 160, ci = r / 5, k = r - ci * 5;
        di = (ci * 5 + k) * 32 + co;
    } else if (b == 4) {
        int o = i / 864, j = i - o * 864;
        int co = j / 27, pq = j - co * 27;
        int idx = pq * 32 + co;
        int oc = o & 31, h = o >> 5;
        di = idx * 64 + oc * 2 + h;
    }
    dst[di] = q;
}

// ---- conv kernel: L1..L4 for TWO sample-pairs, 512 threads -----------------
// smem (u64):
//   ACT(pr) = sm + pr*3140:
//     [0,2052)     H1 [ci*128+t], later H3p [tp*66 + co*2 + par] (alias)
//     [2052,3140)  P1 [ci*68+p]; staging aliases: SX@+2052(258)
//   W1s  = sm+2310 (64, in ACT0's P1 area; dead before L2 writes P1)
//   B1s  = sm+2374 (16)
//   W3f  = sm+6280 (1280 u64 = 2560 floats)
//   W4f  = sm+7560 (2560 u64 = 5120 floats)
//   B2s  = sm+10120(16)  B3s = sm+10136(32)  B4s = sm+10168(32)
#define CONV_SMEM_U64 10200
#define CONV_SMEM_BYTES (CONV_SMEM_U64 * 8)

__global__ void __launch_bounds__(512, 2)
conv_kernel(const float* __restrict__ x,
            const float* __restrict__ b1, const float* __restrict__ b2,
            const float* __restrict__ b3, const float* __restrict__ b4) {
    extern __shared__ u64 sm[];
    const int tid  = threadIdx.x;
    const int wrp  = tid >> 5;
    const int lane = tid & 31;
    const int prW  = wrp >> 3;       // pair index for warp-mapped layers
    const int w8   = wrp & 7;

    u64* W1s = sm + 2310;
    u64* B1s = sm + 2374;
    float* W3f = (float*)(sm + 6280);
    float* W4f = (float*)(sm + 7560);
    u64* B2s = sm + 10120;
    u64* B3s = sm + 10136;
    u64* B4s = sm + 10168;

    // ---- stage inputs + weights --------------------------------------------
    {
        int pr = tid >> 8, rest = tid & 255;
        int c = rest >> 7, t = rest & 127;
        const float* xp = x + (2 * blockIdx.x + pr) * 512 + c * 128 + t;
        (sm + pr * 3140 + 2052)[c * 128 + t] = pack2(xp[0], xp[256]);
    }
    for (int i = tid; i < 640;  i += 512) ((float4*)W3f)[i] = ((const float4*)g_qw3)[i];
    for (int i = tid; i < 1280; i += 512) ((float4*)W4f)[i] = ((const float4*)g_qw4)[i];
    if (tid < 64) W1s[tid] = dup2(g_qw1[tid]);
    else if (tid >= 64 && tid < 80)   B1s[tid - 64] = dup2(b1[tid - 64]);
    else if (tid >= 96 && tid < 112)  B2s[tid - 96] = dup2(b2[tid - 96]);
    else if (tid >= 128 && tid < 160) B3s[tid - 128] = dup2(b3[tid - 128]);
    else if (tid >= 160 && tid < 192) B4s[tid - 160] = dup2(b4[tid - 160]);
    __syncthreads();

    // ---- L1: conv(2->16, k=2) + lrelu, t = 0..126 --------------------------
    if (tid < 508) {
        int cg = tid & 1, pr = (tid >> 1) & 1, t = tid >> 2;
        const u64* SXp = sm + pr * 3140 + 2052;
        u64 a00 = SXp[t], a01 = SXp[t + 1], a10 = SXp[128 + t], a11 = SXp[128 + t + 1];
        u64* o = sm + pr * 3140 + t;
#pragma unroll
        for (int u = 0; u < 8; u++) {
            int co = cg * 8 + u;
            ulonglong2 w01 = lds2(W1s + co * 4);
            ulonglong2 w23 = lds2(W1s + co * 4 + 2);
            u64 acc = B1s[co];
            acc = ffma2(a00, w01.x, acc);
            acc = ffma2(a01, w01.y, acc);
            acc = ffma2(a10, w23.x, acc);
            acc = ffma2(a11, w23.y, acc);
            o[co * 128] = lrelu2(acc);
        }
    }
    __syncthreads();

    // ---- L2: conv(16->16, k=3) + lrelu + pool ------------------------------
    {
        u64* act = sm + prW * 3140;
        int co = lane & 15, half = lane >> 4;
        int t0 = 16 * w8 + 8 * half;
        u64 acc[8];
        u64 bb = B2s[co];
#pragma unroll
        for (int p = 0; p < 8; p++) acc[p] = bb;
        for (int ci = 0; ci < 16; ci++) {
            const u64* h = act + ci * 128 + t0;
            u64 a[10];
#pragma unroll
            for (int s = 0; s < 5; s++) {
                ulonglong2 v = lds2(h + 2 * s);
                a[2 * s] = v.x; a[2 * s + 1] = v.y;
            }
            u64 w0 = dup2(__ldg(g_qw2 + (ci * 3 + 0) * 16 + co));
            u64 w1 = dup2(__ldg(g_qw2 + (ci * 3 + 1) * 16 + co));
            u64 w2 = dup2(__ldg(g_qw2 + (ci * 3 + 2) * 16 + co));
#pragma unroll
            for (int p = 0; p < 8; p++) {
                u64 s = acc[p];
                s = ffma2(a[p],     w0, s);
                s = ffma2(a[p + 1], w1, s);
                s = ffma2(a[p + 2], w2, s);
                acc[p] = s;
            }
        }
        u64* o = act + 2052 + co * 68;
#pragma unroll
        for (int i = 0; i < 4; i++) {
            int pq = 8 * w8 + 4 * half + i;
            if (pq < 62)
                o[pq] = lrelu2(max2(acc[2 * i], acc[2 * i + 1]));
        }
    }
    __syncthreads();

    // ---- L3: conv(16->32, k=5) + lrelu. lane = cout ------------------------
    {
        u64* act = sm + prW * 3140;
        int t0 = 8 * w8;
        u64 acc[8];
        u64 bb = B3s[lane];
#pragma unroll
        for (int p = 0; p < 8; p++) acc[p] = bb;
        for (int ci = 0; ci < 16; ci++) {
            const u64* pb = act + 2052 + ci * 68 + t0;
            u64 a[12];
#pragma unroll
            for (int j = 0; j < 6; j++) {
                ulonglong2 v = lds2(pb + 2 * j);
                a[2 * j] = v.x; a[2 * j + 1] = v.y;
            }
            const float* wf = W3f + ci * 160 + lane;
            u64 w0 = dup2(wf[0]),  w1 = dup2(wf[32]), w2 = dup2(wf[64]);
            u64 w3 = dup2(wf[96]), w4 = dup2(wf[128]);
#pragma unroll
            for (int p = 0; p < 8; p++) {
                u64 s = acc[p];
                s = ffma2(a[p],     w0, s);
                s = ffma2(a[p + 1], w1, s);
                s = ffma2(a[p + 2], w2, s);
                s = ffma2(a[p + 3], w3, s);
                s = ffma2(a[p + 4], w4, s);
                acc[p] = s;
            }
        }
        u64* ob = act + lane * 2;
#pragma unroll
        for (int i = 0; i < 4; i++) {
            int tp = 4 * w8 + i;
            if (tp < 29) {
                ulonglong2 v;
                v.x = lrelu2(acc[2 * i]);
                v.y = lrelu2(acc[2 * i + 1]);
                *reinterpret_cast<ulonglong2*>(ob + tp * 66) = v;
            }
        }
    }
    __syncthreads();

    // ---- L4: conv(32->32, k=5) + lrelu + pool -> global P2 -----------------
    if (w8 < 7) {
        u64* act = sm + prW * 3140;
        int tp0 = 4 * w8;
        u64 acc[8];
        u64 bb = B4s[lane];
#pragma unroll
        for (int p = 0; p < 8; p++) acc[p] = bb;
        for (int ci = 0; ci < 32; ci++) {
            const u64* pb = act + tp0 * 66 + ci * 2;
            u64 a[12];
#pragma unroll
            for (int j = 0; j < 6; j++) {
                ulonglong2 v = lds2(pb + j * 66);
                a[2 * j] = v.x; a[2 * j + 1] = v.y;
            }
            const float* wf = W4f + ci * 160 + lane;
            u64 w0 = dup2(wf[0]),  w1 = dup2(wf[32]), w2 = dup2(wf[64]);
            u64 w3 = dup2(wf[96]), w4 = dup2(wf[128]);
#pragma unroll
            for (int p = 0; p < 8; p++) {
                u64 s = acc[p];
                s = ffma2(a[p],     w0, s);
                s = ffma2(a[p + 1], w1, s);
                s = ffma2(a[p + 2], w2, s);
                s = ffma2(a[p + 3], w3, s);
                s = ffma2(a[p + 4], w4, s);
                acc[p] = s;
            }
        }
        u64* ob = g_P2 + (2 * blockIdx.x + prW) * 864 + lane;
#pragma unroll
        for (int i = 0; i < 4; i++) {
            int pq = 4 * w8 + i;
            if (pq < 27)
                ob[pq * 32] = lrelu2(max2(acc[2 * i], acc[2 * i + 1]));
        }
    }
}

// ---- dense kernel: 864->64->1 for 4 pairs (8 samples) ----------------------
// smem (u64): SP2 [0,3456) [q*864+j]; PART [3456,5504); HH [5504,5760)
#define DENSE_SMEM_U64 5760
#define DENSE_SMEM_BYTES (DENSE_SMEM_U64 * 8)

__global__ void __launch_bounds__(256, 4)
dense_kernel(const float* __restrict__ bd, const float* __restrict__ bo,
             float* __restrict__ out) {
    extern __shared__ u64 sm[];
    const int tid  = threadIdx.x;
    const int wrp  = tid >> 5;
    const int lane = tid & 31;
    const int blk  = blockIdx.x;

    u64* SP2  = sm;
    u64* PART = sm + 3456;
    u64* HH   = sm + 5504;

    // stage 4 pairs of P2 rows
#pragma unroll 2
    for (int i = tid; i < 1728; i += 256) {
        int q = i / 432, r = i - q * 432;
        ulonglong2 v = __ldg((const ulonglong2*)(g_P2 + (blk * 4 + q) * 864) + r);
        *reinterpret_cast<ulonglong2*>(SP2 + q * 864 + 2 * r) = v;
    }
    __syncthreads();

    // 8 warps x 108-j chunks; lane covers (oc, oc+32) for 4 pairs
    {
        int j0 = wrp * 108;
        const float2* wdp = (const float2*)g_qwd;   // [idx][oc] = (w_oc, w_oc+32)
        u64 acc[8] = {0, 0, 0, 0, 0, 0, 0, 0};      // [q*2 + h]
#pragma unroll 4
        for (int g = 0; g < 54; g++) {
            int j = j0 + 2 * g;
            float2 wa = __ldg(wdp + j * 32 + lane);
            float2 wb = __ldg(wdp + (j + 1) * 32 + lane);
            u64 w0a = dup2(wa.x), w0b = dup2(wa.y);
            u64 w1a = dup2(wb.x), w1b = dup2(wb.y);
#pragma unroll
            for (int q = 0; q < 4; q++) {
                ulonglong2 a = lds2(SP2 + q * 864 + j);
                acc[q*2]   = ffma2(a.x, w0a, acc[q*2]);
                acc[q*2]   = ffma2(a.y, w1a, acc[q*2]);
                acc[q*2+1] = ffma2(a.x, w0b, acc[q*2+1]);
                acc[q*2+1] = ffma2(a.y, w1b, acc[q*2+1]);
            }
        }
        u64* pb = PART + wrp * 256;
#pragma unroll
        for (int q = 0; q < 4; q++) {
            pb[lane * 4 + q]        = acc[q*2];
            pb[(lane + 32) * 4 + q] = acc[q*2+1];
        }
    }
    __syncthreads();

    // reduce 8 chunks + bias + lrelu
    {
        int oc = tid & 63, q = tid >> 6;
        u64 s = PART[oc * 4 + q];
#pragma unroll
        for (int c = 1; c < 8; c++) s = add2(s, PART[c * 256 + oc * 4 + q]);
        s = add2(s, dup2(bd[oc]));
        HH[q * 64 + oc] = lrelu2(s);
    }
    __syncthreads();

    // output 64 -> 1
    if (tid < 128) {
        int q = tid >> 5, ln = tid & 31;
        float2 h0  = unpack2(HH[q * 64 + ln]);
        float2 h1v = unpack2(HH[q * 64 + 32 + ln]);
        float wl = g_qwo[ln], wh = g_qwo[ln + 32];
        float ax = h0.x * wl + h1v.x * wh;
        float ay = h0.y * wl + h1v.y * wh;
#pragma unroll
        for (int o = 16; o > 0; o >>= 1) {
            ax += __shfl_xor_sync(0xffffffffu, ax, o);
            ay += __shfl_xor_sync(0xffffffffu, ay, o);
        }
        if (ln == 0) {
            float bov = bo[0];
            reinterpret_cast<float2*>(out)[blk * 4 + q] =
                make_float2(ax + bov, ay + bov);
        }
    }
}

// ---- launcher --------------------------------------------------------------
extern "C" void kernel_launch(void* const* d_in, const int* in_sizes, int n_in,
                              void* d_out, int out_size) {
    const float* x  = (const float*)d_in[0];
    const float* w1 = (const float*)d_in[1];
    const float* b1 = (const float*)d_in[2];
    const float* w2 = (const float*)d_in[3];
    const float* b2 = (const float*)d_in[4];
    const float* w3 = (const float*)d_in[5];
    const float* b3 = (const float*)d_in[6];
    const float* w4 = (const float*)d_in[7];
    const float* b4 = (const float*)d_in[8];
    const float* wd = (const float*)d_in[9];
    const float* bd = (const float*)d_in[10];
    const float* wo = (const float*)d_in[11];
    const float* bo = (const float*)d_in[12];

    cudaFuncSetAttribute(conv_kernel,
                         cudaFuncAttributeMaxDynamicSharedMemorySize, CONV_SMEM_BYTES);
    cudaFuncSetAttribute(dense_kernel,
                         cudaFuncAttributeMaxDynamicSharedMemorySize, DENSE_SMEM_BYTES);

    scale_kernel<<<6, 256>>>(w1, w2, w3, w4, wd, wo);
    quantize_kernel<<<251, 256>>>(w1, w2, w3, w4, wd, wo);
    conv_kernel<<<8192, 512, CONV_SMEM_BYTES>>>(x, b1, b2, b3, b4);
    dense_kernel<<<4096, 256, DENSE_SMEM_BYTES>>>(bd, bo, (float*)d_out);
}

// round 13
// speedup vs baseline: 1.0406x; 1.0406x over previous
#include <cuda_runtime.h>
#include <cuda_bf16.h>

// ----------------------------------------------------------------------------
// QCNN, round 13: conv reverted to round-10 (256 thr, 1 pair, 4 CTAs/SM —
// the 2-pair merge regressed via barrier coupling); dense keeps
// launch_bounds(256,4) from round 12 (101us, occ 46%).
// ----------------------------------------------------------------------------

typedef unsigned long long u64;

__device__ __align__(16) float g_qw1[64];      // [co*4 + ci*2 + k]
__device__ __align__(16) float g_qw2[768];     // [(ci*3+k)*16 + co]
__device__ __align__(16) float g_qw3[2560];    // [(ci*5+k)*32 + co]
__device__ __align__(16) float g_qw4[5120];    // [(ci*5+k)*32 + co]
__device__ __align__(16) float g_qwd[55296];   // [idx=pq*32+co][oc*2+h]  h: +32
__device__ __align__(16) float g_qwo[64];
__device__ float g_scale[6];
__device__ __align__(16) u64   g_P2[16384 * 864];  // [pair][pq*32+co] f32x2

// ---- f32x2 helpers ---------------------------------------------------------
__device__ __forceinline__ u64 ffma2(u64 a, u64 b, u64 c) {
    u64 d;
    asm("fma.rn.f32x2 %0, %1, %2, %3;" : "=l"(d) : "l"(a), "l"(b), "l"(c));
    return d;
}
__device__ __forceinline__ u64 add2(u64 a, u64 b) {
    u64 d;
    asm("add.rn.f32x2 %0, %1, %2;" : "=l"(d) : "l"(a), "l"(b));
    return d;
}
__device__ __forceinline__ u64 pack2(float x, float y) {
    u64 d;
    asm("mov.b64 %0, {%1, %2};" : "=l"(d) : "f"(x), "f"(y));
    return d;
}
__device__ __forceinline__ float2 unpack2(u64 v) {
    float2 f;
    asm("mov.b64 {%0, %1}, %2;" : "=f"(f.x), "=f"(f.y) : "l"(v));
    return f;
}
__device__ __forceinline__ u64 dup2(float w) { return pack2(w, w); }
__device__ __forceinline__ u64 lrelu2(u64 v) {
    float2 f = unpack2(v);
    f.x = f.x > 0.0f ? f.x : 0.1f * f.x;
    f.y = f.y > 0.0f ? f.y : 0.1f * f.y;
    return pack2(f.x, f.y);
}
__device__ __forceinline__ u64 max2(u64 a, u64 b) {
    float2 fa = unpack2(a), fb = unpack2(b);
    return pack2(fmaxf(fa.x, fb.x), fmaxf(fa.y, fb.y));
}
__device__ __forceinline__ ulonglong2 lds2(const u64* p) {
    return *reinterpret_cast<const ulonglong2*>(p);
}

// ---- prep phase A: per-tensor scale (max|w| / 127) -------------------------
__global__ void scale_kernel(const float* __restrict__ w1,
                             const float* __restrict__ w2,
                             const float* __restrict__ w3,
                             const float* __restrict__ w4,
                             const float* __restrict__ wd,
                             const float* __restrict__ wo) {
    __shared__ float red[256];
    int b = blockIdx.x, tid = threadIdx.x;
    const float* src; int n;
    if (b == 0)      { src = w1; n = 64; }
    else if (b == 1) { src = w2; n = 768; }
    else if (b == 2) { src = w3; n = 2560; }
    else if (b == 3) { src = w4; n = 5120; }
    else if (b == 4) { src = wd; n = 55296; }
    else             { src = wo; n = 64; }
    float m = 0.0f;
    for (int i = tid; i < n; i += 256) m = fmaxf(m, fabsf(src[i]));
    red[tid] = m;
    __syncthreads();
    for (int s = 128; s > 0; s >>= 1) {
        if (tid < s) red[tid] = fmaxf(red[tid], red[tid + s]);
        __syncthreads();
    }
    if (tid == 0) g_scale[b] = red[0] / 127.0f;
}

// ---- prep phase B: quantize + permute, fully parallel ----------------------
__global__ void quantize_kernel(const float* __restrict__ w1,
                                const float* __restrict__ w2,
                                const float* __restrict__ w3,
                                const float* __restrict__ w4,
                                const float* __restrict__ wd,
                                const float* __restrict__ wo) {
    int blk = blockIdx.x, tid = threadIdx.x;
    int b, i;
    const float* src; float* dst; int n;
    if (blk < 1)        { b = 0; src = w1; dst = g_qw1; n = 64;    i = blk * 256 + tid; }
    else if (blk < 4)   { b = 1; src = w2; dst = g_qw2; n = 768;   i = (blk - 1) * 256 + tid; }
    else if (blk < 14)  { b = 2; src = w3; dst = g_qw3; n = 2560;  i = (blk - 4) * 256 + tid; }
    else if (blk < 34)  { b = 3; src = w4; dst = g_qw4; n = 5120;  i = (blk - 14) * 256 + tid; }
    else if (blk < 250) { b = 4; src = wd; dst = g_qwd; n = 55296; i = (blk - 34) * 256 + tid; }
    else                { b = 5; src = wo; dst = g_qwo; n = 64;    i = (blk - 250) * 256 + tid; }
    if (i >= n) return;
    float scale = g_scale[b];
    float q = rintf(src[i] / scale);               // round half-even == jnp.round
    q = fminf(fmaxf(q, -127.0f), 127.0f) * scale;
    int di = i;
    if (b == 1) {
        int co = i / 48, r = i - co * 48, ci = r / 3, k = r - ci * 3;
        di = (ci * 3 + k) * 16 + co;
    } else if (b == 2) {
        int co = i / 80, r = i - co * 80, ci = r / 5, k = r - ci * 5;
        di = (ci * 5 + k) * 32 + co;
    } else if (b == 3) {
        int co = i / 160, r = i - co * 160, ci = r / 5, k = r - ci * 5;
        di = (ci * 5 + k) * 32 + co;
    } else if (b == 4) {
        int o = i / 864, j = i - o * 864;
        int co = j / 27, pq = j - co * 27;
        int idx = pq * 32 + co;
        int oc = o & 31, h = o >> 5;
        di = idx * 64 + oc * 2 + h;
    }
    dst[di] = q;
}

// ---- conv kernel: L1..L4 for one sample-pair (round-10 validated) ----------
#define CONV_SMEM_U64 7060
#define CONV_SMEM_BYTES (CONV_SMEM_U64 * 8)

__global__ void __launch_bounds__(256, 4)
conv_kernel(const float* __restrict__ x,
            const float* __restrict__ b1, const float* __restrict__ b2,
            const float* __restrict__ b3, const float* __restrict__ b4) {
    extern __shared__ u64 sm[];
    const int tid  = threadIdx.x;
    const int wrp  = tid >> 5;
    const int lane = tid & 31;
    const int pair = blockIdx.x;

    u64* H1  = sm;
    u64* H3p = sm;
    u64* P1  = sm + 2052;
    u64* SX  = sm + 2052;
    u64* W1s = sm + 2310;
    u64* B1s = sm + 2374;
    float* W3f = (float*)(sm + 3140);
    float* W4f = (float*)(sm + 4420);
    u64* B2s = sm + 6980;
    u64* B3s = sm + 6996;
    u64* B4s = sm + 7028;

    {
        int c = tid >> 7, t = tid & 127;
        const float* xp = x + pair * 512 + c * 128 + t;
        SX[c * 128 + t] = pack2(xp[0], xp[256]);
    }
    for (int i = tid; i < 640;  i += 256) ((float4*)W3f)[i] = ((const float4*)g_qw3)[i];
    for (int i = tid; i < 1280; i += 256) ((float4*)W4f)[i] = ((const float4*)g_qw4)[i];
    if (tid < 64) W1s[tid] = dup2(g_qw1[tid]);
    else if (tid >= 64 && tid < 80)   B1s[tid - 64] = dup2(b1[tid - 64]);
    else if (tid >= 96 && tid < 112)  B2s[tid - 96] = dup2(b2[tid - 96]);
    else if (tid >= 128 && tid < 160) B3s[tid - 128] = dup2(b3[tid - 128]);
    else if (tid >= 160 && tid < 192) B4s[tid - 160] = dup2(b4[tid - 160]);
    __syncthreads();

    // L1
    if (tid < 254) {
        int cg = tid & 1, t = tid >> 1;
        u64 a00 = SX[t], a01 = SX[t + 1], a10 = SX[128 + t], a11 = SX[128 + t + 1];
        u64* o = H1 + t;
#pragma unroll
        for (int u = 0; u < 8; u++) {
            int co = cg * 8 + u;
            ulonglong2 w01 = lds2(W1s + co * 4);
            ulonglong2 w23 = lds2(W1s + co * 4 + 2);
            u64 acc = B1s[co];
            acc = ffma2(a00, w01.x, acc);
            acc = ffma2(a01, w01.y, acc);
            acc = ffma2(a10, w23.x, acc);
            acc = ffma2(a11, w23.y, acc);
            o[co * 128] = lrelu2(acc);
        }
    }
    __syncthreads();

    // L2
    {
        int co = lane & 15, half = lane >> 4;
        int t0 = 16 * wrp + 8 * half;
        u64 acc[8];
        u64 bb = B2s[co];
#pragma unroll
        for (int p = 0; p < 8; p++) acc[p] = bb;
        for (int ci = 0; ci < 16; ci++) {
            const u64* h = H1 + ci * 128 + t0;
            u64 a[10];
#pragma unroll
            for (int s = 0; s < 5; s++) {
                ulonglong2 v = lds2(h + 2 * s);
                a[2 * s] = v.x; a[2 * s + 1] = v.y;
            }
            u64 w0 = dup2(__ldg(g_qw2 + (ci * 3 + 0) * 16 + co));
            u64 w1 = dup2(__ldg(g_qw2 + (ci * 3 + 1) * 16 + co));
            u64 w2 = dup2(__ldg(g_qw2 + (ci * 3 + 2) * 16 + co));
#pragma unroll
            for (int p = 0; p < 8; p++) {
                u64 s = acc[p];
                s = ffma2(a[p],     w0, s);
                s = ffma2(a[p + 1], w1, s);
                s = ffma2(a[p + 2], w2, s);
                acc[p] = s;
            }
        }
        u64* o = P1 + co * 68;
#pragma unroll
        for (int i = 0; i < 4; i++) {
            int pq = 8 * wrp + 4 * half + i;
            if (pq < 62)
                o[pq] = lrelu2(max2(acc[2 * i], acc[2 * i + 1]));
        }
    }
    __syncthreads();

    // L3
    {
        int t0 = 8 * wrp;
        u64 acc[8];
        u64 bb = B3s[lane];
#pragma unroll
        for (int p = 0; p < 8; p++) acc[p] = bb;
        for (int ci = 0; ci < 16; ci++) {
            const u64* pb = P1 + ci * 68 + t0;
            u64 a[12];
#pragma unroll
            for (int j = 0; j < 6; j++) {
                ulonglong2 v = lds2(pb + 2 * j);
                a[2 * j] = v.x; a[2 * j + 1] = v.y;
            }
            const float* wf = W3f + ci * 160 + lane;
            u64 w0 = dup2(wf[0]),  w1 = dup2(wf[32]), w2 = dup2(wf[64]);
            u64 w3 = dup2(wf[96]), w4 = dup2(wf[128]);
#pragma unroll
            for (int p = 0; p < 8; p++) {
                u64 s = acc[p];
                s = ffma2(a[p],     w0, s);
                s = ffma2(a[p + 1], w1, s);
                s = ffma2(a[p + 2], w2, s);
                s = ffma2(a[p + 3], w3, s);
                s = ffma2(a[p + 4], w4, s);
                acc[p] = s;
            }
        }
        u64* ob = H3p + lane * 2;
#pragma unroll
        for (int i = 0; i < 4; i++) {
            int tp = 4 * wrp + i;
            if (tp < 29) {
                ulonglong2 v;
                v.x = lrelu2(acc[2 * i]);
                v.y = lrelu2(acc[2 * i + 1]);
                *reinterpret_cast<ulonglong2*>(ob + tp * 66) = v;
            }
        }
    }
    __syncthreads();

    // L4 -> global P2
    if (wrp < 7) {
        int tp0 = 4 * wrp;
        u64 acc[8];
        u64 bb = B4s[lane];
#pragma unroll
        for (int p = 0; p < 8; p++) acc[p] = bb;
        for (int ci = 0; ci < 32; ci++) {
            const u64* pb = H3p + tp0 * 66 + ci * 2;
            u64 a[12];
#pragma unroll
            for (int j = 0; j < 6; j++) {
                ulonglong2 v = lds2(pb + j * 66);
                a[2 * j] = v.x; a[2 * j + 1] = v.y;
            }
            const float* wf = W4f + ci * 160 + lane;
            u64 w0 = dup2(wf[0]),  w1 = dup2(wf[32]), w2 = dup2(wf[64]);
            u64 w3 = dup2(wf[96]), w4 = dup2(wf[128]);
#pragma unroll
            for (int p = 0; p < 8; p++) {
                u64 s = acc[p];
                s = ffma2(a[p],     w0, s);
                s = ffma2(a[p + 1], w1, s);
                s = ffma2(a[p + 2], w2, s);
                s = ffma2(a[p + 3], w3, s);
                s = ffma2(a[p + 4], w4, s);
                acc[p] = s;
            }
        }
        u64* ob = g_P2 + pair * 864 + lane;
#pragma unroll
        for (int i = 0; i < 4; i++) {
            int pq = 4 * wrp + i;
            if (pq < 27)
                ob[pq * 32] = lrelu2(max2(acc[2 * i], acc[2 * i + 1]));
        }
    }
}

// ---- dense kernel: 864->64->1 for 4 pairs (8 samples), 4 CTAs/SM -----------
// smem (u64): SP2 [0,3456) [q*864+j]; PART [3456,5504); HH [5504,5760)
#define DENSE_SMEM_U64 5760
#define DENSE_SMEM_BYTES (DENSE_SMEM_U64 * 8)

__global__ void __launch_bounds__(256, 4)
dense_kernel(const float* __restrict__ bd, const float* __restrict__ bo,
             float* __restrict__ out) {
    extern __shared__ u64 sm[];
    const int tid  = threadIdx.x;
    const int wrp  = tid >> 5;
    const int lane = tid & 31;
    const int blk  = blockIdx.x;

    u64* SP2  = sm;
    u64* PART = sm + 3456;
    u64* HH   = sm + 5504;

    // stage 4 pairs of P2 rows
#pragma unroll 2
    for (int i = tid; i < 1728; i += 256) {
        int q = i / 432, r = i - q * 432;
        ulonglong2 v = __ldg((const ulonglong2*)(g_P2 + (blk * 4 + q) * 864) + r);
        *reinterpret_cast<ulonglong2*>(SP2 + q * 864 + 2 * r) = v;
    }
    __syncthreads();

    // 8 warps x 108-j chunks; lane covers (oc, oc+32) for 4 pairs
    {
        int j0 = wrp * 108;
        const float2* wdp = (const float2*)g_qwd;   // [idx][oc] = (w_oc, w_oc+32)
        u64 acc[8] = {0, 0, 0, 0, 0, 0, 0, 0};      // [q*2 + h]
#pragma unroll 4
        for (int g = 0; g < 54; g++) {
            int j = j0 + 2 * g;
            float2 wa = __ldg(wdp + j * 32 + lane);
            float2 wb = __ldg(wdp + (j + 1) * 32 + lane);
            u64 w0a = dup2(wa.x), w0b = dup2(wa.y);
            u64 w1a = dup2(wb.x), w1b = dup2(wb.y);
#pragma unroll
            for (int q = 0; q < 4; q++) {
                ulonglong2 a = lds2(SP2 + q * 864 + j);
                acc[q*2]   = ffma2(a.x, w0a, acc[q*2]);
                acc[q*2]   = ffma2(a.y, w1a, acc[q*2]);
                acc[q*2+1] = ffma2(a.x, w0b, acc[q*2+1]);
                acc[q*2+1] = ffma2(a.y, w1b, acc[q*2+1]);
            }
        }
        u64* pb = PART + wrp * 256;
#pragma unroll
        for (int q = 0; q < 4; q++) {
            pb[lane * 4 + q]        = acc[q*2];
            pb[(lane + 32) * 4 + q] = acc[q*2+1];
        }
    }
    __syncthreads();

    // reduce 8 chunks + bias + lrelu
    {
        int oc = tid & 63, q = tid >> 6;
        u64 s = PART[oc * 4 + q];
#pragma unroll
        for (int c = 1; c < 8; c++) s = add2(s, PART[c * 256 + oc * 4 + q]);
        s = add2(s, dup2(bd[oc]));
        HH[q * 64 + oc] = lrelu2(s);
    }
    __syncthreads();

    // output 64 -> 1
    if (tid < 128) {
        int q = tid >> 5, ln = tid & 31;
        float2 h0  = unpack2(HH[q * 64 + ln]);
        float2 h1v = unpack2(HH[q * 64 + 32 + ln]);
        float wl = g_qwo[ln], wh = g_qwo[ln + 32];
        float ax = h0.x * wl + h1v.x * wh;
        float ay = h0.y * wl + h1v.y * wh;
#pragma unroll
        for (int o = 16; o > 0; o >>= 1) {
            ax += __shfl_xor_sync(0xffffffffu, ax, o);
            ay += __shfl_xor_sync(0xffffffffu, ay, o);
        }
        if (ln == 0) {
            float bov = bo[0];
            reinterpret_cast<float2*>(out)[blk * 4 + q] =
                make_float2(ax + bov, ay + bov);
        }
    }
}

// ---- launcher --------------------------------------------------------------
extern "C" void kernel_launch(void* const* d_in, const int* in_sizes, int n_in,
                              void* d_out, int out_size) {
    const float* x  = (const float*)d_in[0];
    const float* w1 = (const float*)d_in[1];
    const float* b1 = (const float*)d_in[2];
    const float* w2 = (const float*)d_in[3];
    const float* b2 = (const float*)d_in[4];
    const float* w3 = (const float*)d_in[5];
    const float* b3 = (const float*)d_in[6];
    const float* w4 = (const float*)d_in[7];
    const float* b4 = (const float*)d_in[8];
    const float* wd = (const float*)d_in[9];
    const float* bd = (const float*)d_in[10];
    const float* wo = (const float*)d_in[11];
    const float* bo = (const float*)d_in[12];

    cudaFuncSetAttribute(conv_kernel,
                         cudaFuncAttributeMaxDynamicSharedMemorySize, CONV_SMEM_BYTES);
    cudaFuncSetAttribute(dense_kernel,
                         cudaFuncAttributeMaxDynamicSharedMemorySize, DENSE_SMEM_BYTES);

    scale_kernel<<<6, 256>>>(w1, w2, w3, w4, wd, wo);
    quantize_kernel<<<251, 256>>>(w1, w2, w3, w4, wd, wo);
    conv_kernel<<<16384, 256, CONV_SMEM_BYTES>>>(x, b1, b2, b3, b4);
    dense_kernel<<<4096, 256, DENSE_SMEM_BYTES>>>(bd, bo, (float*)d_out);
}